// round 1
// baseline (speedup 1.0000x reference)
#include <cuda_runtime.h>
#include <math.h>

#define BB 4
#define NN 2048
#define DIMM 512
#define HH 8
#define DHH 64
#define QKVN (3*HH*DHH)   // 1536
#define ATTN_SCALE 0.125f // 64^-0.5

// ---------------- scratch (device globals; allocation-free rule) ----------------
__device__ float g_q[BB*HH*NN*DHH];                 // [b][h][n][d]
__device__ float g_k[BB*HH*NN*DHH];
__device__ float g_v[BB*HH*NN*DHH];
__device__ float g_dots[(size_t)BB*NN*HH*NN];       // [b][n][h][m]  537MB
__device__ float g_attn[(size_t)BB*HH*NN*NN];       // [b][g][n][m]  537MB
__device__ float g_ctx[BB*NN*HH*DHH];               // [b][n][g*64+d]

// =====================================================================
// K1: qkv = x(8192x512) @ w(512x1536) + bias  -> scatter to q/k/v [b][h][n][d]
// 128x128 tile, BK=16, 8x8 micro-tile, 256 threads
// =====================================================================
__global__ __launch_bounds__(256) void gemm_qkv(const float* __restrict__ x,
                                                const float* __restrict__ w,
                                                const float* __restrict__ bias) {
    const int Kd = DIMM, Nout = QKVN;
    __shared__ float As[16][128+4];
    __shared__ float Bs[16][128];
    int bm = blockIdx.y * 128, bn = blockIdx.x * 128;
    int tid = threadIdx.x;
    int tx = tid % 16, ty = tid / 16;
    float acc[8][8] = {};
    for (int k0 = 0; k0 < Kd; k0 += 16) {
        for (int l = tid; l < 128*16; l += 256) {
            int r = l / 16, c = l % 16;
            As[c][r] = x[(size_t)(bm + r) * Kd + k0 + c];
        }
        for (int l = tid; l < 16*128; l += 256) {
            int r = l / 128, c = l % 128;
            Bs[r][c] = w[(size_t)(k0 + r) * Nout + bn + c];
        }
        __syncthreads();
        #pragma unroll
        for (int k = 0; k < 16; k++) {
            float ra[8], rb[8];
            #pragma unroll
            for (int i = 0; i < 8; i++) ra[i] = As[k][ty*8 + i];
            #pragma unroll
            for (int j = 0; j < 8; j++) rb[j] = Bs[k][tx*8 + j];
            #pragma unroll
            for (int i = 0; i < 8; i++)
                #pragma unroll
                for (int j = 0; j < 8; j++)
                    acc[i][j] += ra[i] * rb[j];
        }
        __syncthreads();
    }
    #pragma unroll
    for (int i = 0; i < 8; i++) {
        int row = bm + ty*8 + i;               // row = b*N + n
        int b_ = row >> 11, n_ = row & (NN - 1);
        #pragma unroll
        for (int j = 0; j < 8; j++) {
            int col = bn + tx*8 + j;
            float vv = acc[i][j] + bias[col];
            int which = col / (HH*DHH);
            int hh = (col % (HH*DHH)) / DHH;
            int dd = col % DHH;
            size_t idx = (((size_t)(b_*HH + hh)) * NN + n_) * DHH + dd;
            if (which == 0)      g_q[idx] = vv;
            else if (which == 1) g_k[idx] = vv;
            else                 g_v[idx] = vv;
        }
    }
}

// =====================================================================
// K2: per (b,h): dots[b][n][h][m] = SCALE * q[n,:]·k[m,:]
// =====================================================================
__global__ __launch_bounds__(256) void gemm_qk() {
    int bh = blockIdx.z;                        // 0..31
    const float* Q  = g_q + (size_t)bh * NN * DHH;
    const float* Km = g_k + (size_t)bh * NN * DHH;
    int b_ = bh / HH, h_ = bh % HH;
    __shared__ float As[16][128+4];
    __shared__ float Bs[16][128+4];
    int bm = blockIdx.y * 128, bn = blockIdx.x * 128;
    int tid = threadIdx.x;
    int tx = tid % 16, ty = tid / 16;
    float acc[8][8] = {};
    for (int k0 = 0; k0 < DHH; k0 += 16) {
        for (int l = tid; l < 128*16; l += 256) {
            int r = l / 16, c = l % 16;
            As[c][r] = Q[(size_t)(bm + r) * DHH + k0 + c];
        }
        for (int l = tid; l < 128*16; l += 256) {
            int r = l / 16, c = l % 16;
            Bs[c][r] = Km[(size_t)(bn + r) * DHH + k0 + c];
        }
        __syncthreads();
        #pragma unroll
        for (int k = 0; k < 16; k++) {
            float ra[8], rb[8];
            #pragma unroll
            for (int i = 0; i < 8; i++) ra[i] = As[k][ty*8 + i];
            #pragma unroll
            for (int j = 0; j < 8; j++) rb[j] = Bs[k][tx*8 + j];
            #pragma unroll
            for (int i = 0; i < 8; i++)
                #pragma unroll
                for (int j = 0; j < 8; j++)
                    acc[i][j] += ra[i] * rb[j];
        }
        __syncthreads();
    }
    #pragma unroll
    for (int i = 0; i < 8; i++) {
        int n_ = bm + ty*8 + i;
        size_t base = (((size_t)(b_*NN + n_)) * HH + h_) * NN;
        #pragma unroll
        for (int j = 0; j < 8; j++) {
            int m_ = bn + tx*8 + j;
            g_dots[base + m_] = acc[i][j] * ATTN_SCALE;
        }
    }
}

// =====================================================================
// K3: per (b,n): th1-mix across heads, softmax over m, th2-mix, write attn2
// 1 CTA per (b,n); 64KB dynamic smem holds the mixed 8x2048 row.
// =====================================================================
__global__ __launch_bounds__(256) void softmax_mix(const float* __restrict__ th1,
                                                   const float* __restrict__ th2) {
    extern __shared__ float s2[];                // [H][N] = 8*2048 floats
    __shared__ float red[256];
    __shared__ float th1s[HH*HH], th2s[HH*HH], cgh[HH*HH];
    __shared__ float rowsum[HH];
    int bid = blockIdx.x;
    int b_ = bid >> 11, n_ = bid & (NN - 1);
    int tid = threadIdx.x;
    if (tid < HH*HH) { th1s[tid] = th1[tid]; th2s[tid] = th2[tid]; }
    __syncthreads();
    const float* drow = g_dots + ((size_t)(b_*NN + n_)) * HH * NN;   // [h][m]

    // phase 1: pre-softmax head mixing
    for (int m = tid; m < NN; m += 256) {
        float dv[HH];
        #pragma unroll
        for (int h = 0; h < HH; h++) dv[h] = drow[(size_t)h * NN + m];
        #pragma unroll
        for (int g = 0; g < HH; g++) {
            float s = 0.f;
            #pragma unroll
            for (int h = 0; h < HH; h++) s += th1s[g*HH + h] * dv[h];
            s2[g*NN + m] = s;
        }
    }
    __syncthreads();

    // phase 2: softmax stats per mixed head
    for (int g = 0; g < HH; g++) {
        float mx = -INFINITY;
        for (int m = tid; m < NN; m += 256) mx = fmaxf(mx, s2[g*NN + m]);
        red[tid] = mx; __syncthreads();
        for (int s = 128; s > 0; s >>= 1) {
            if (tid < s) red[tid] = fmaxf(red[tid], red[tid + s]);
            __syncthreads();
        }
        float gm = red[0];
        __syncthreads();
        float sm = 0.f;
        for (int m = tid; m < NN; m += 256) {
            float e = __expf(s2[g*NN + m] - gm);
            s2[g*NN + m] = e;
            sm += e;
        }
        red[tid] = sm; __syncthreads();
        for (int s = 128; s > 0; s >>= 1) {
            if (tid < s) red[tid] += red[tid + s];
            __syncthreads();
        }
        if (tid == 0) rowsum[g] = red[0];
        __syncthreads();
    }
    // fold 1/L into th2
    if (tid < HH*HH) {
        int h = tid % HH;
        cgh[tid] = th2s[tid] / rowsum[h];
    }
    __syncthreads();

    // phase 3: post-softmax mixing, write [b][g][n][m]
    for (int m = tid; m < NN; m += 256) {
        float ev[HH];
        #pragma unroll
        for (int h = 0; h < HH; h++) ev[h] = s2[h*NN + m];
        #pragma unroll
        for (int g = 0; g < HH; g++) {
            float s = 0.f;
            #pragma unroll
            for (int h = 0; h < HH; h++) s += cgh[g*HH + h] * ev[h];
            g_attn[(((size_t)(b_*HH + g)) * NN + n_) * NN + m] = s;
        }
    }
}

// =====================================================================
// K4: per (b,g): ctx[n][d] = attn2[n][:] @ v[:,d]   (2048x2048 @ 2048x64)
// 128x64 tile, BK=16, 8x4 micro-tile, 256 threads
// =====================================================================
__global__ __launch_bounds__(256) void gemm_av() {
    int bg = blockIdx.z;
    const float* Amat = g_attn + (size_t)bg * NN * NN;
    const float* V    = g_v    + (size_t)bg * NN * DHH;
    int b_ = bg / HH, g_ = bg % HH;
    __shared__ float As[16][128+4];
    __shared__ float Bs[16][64];
    int bm = blockIdx.y * 128;
    int tid = threadIdx.x;
    int tx = tid % 16, ty = tid / 16;    // cols tx*4.., rows ty*8..
    float acc[8][4] = {};
    for (int k0 = 0; k0 < NN; k0 += 16) {
        for (int l = tid; l < 128*16; l += 256) {
            int r = l / 16, c = l % 16;
            As[c][r] = Amat[(size_t)(bm + r) * NN + k0 + c];
        }
        for (int l = tid; l < 16*64; l += 256) {
            int r = l / 64, c = l % 64;
            Bs[r][c] = V[(size_t)(k0 + r) * DHH + c];
        }
        __syncthreads();
        #pragma unroll
        for (int k = 0; k < 16; k++) {
            float ra[8], rb[4];
            #pragma unroll
            for (int i = 0; i < 8; i++) ra[i] = As[k][ty*8 + i];
            #pragma unroll
            for (int j = 0; j < 4; j++) rb[j] = Bs[k][tx*4 + j];
            #pragma unroll
            for (int i = 0; i < 8; i++)
                #pragma unroll
                for (int j = 0; j < 4; j++)
                    acc[i][j] += ra[i] * rb[j];
        }
        __syncthreads();
    }
    #pragma unroll
    for (int i = 0; i < 8; i++) {
        int n_ = bm + ty*8 + i;
        size_t base = ((size_t)(b_*NN + n_)) * (HH*DHH) + g_*DHH;
        #pragma unroll
        for (int j = 0; j < 4; j++) {
            g_ctx[base + tx*4 + j] = acc[i][j];
        }
    }
}

// =====================================================================
// K5: y = ctx(8192x512) @ w_out(512x512) + b_out
// =====================================================================
__global__ __launch_bounds__(256) void gemm_out(const float* __restrict__ w,
                                                const float* __restrict__ bias,
                                                float* __restrict__ out) {
    const int Kd = HH*DHH, Nout = DIMM;
    __shared__ float As[16][128+4];
    __shared__ float Bs[16][128];
    int bm = blockIdx.y * 128, bn = blockIdx.x * 128;
    int tid = threadIdx.x;
    int tx = tid % 16, ty = tid / 16;
    float acc[8][8] = {};
    for (int k0 = 0; k0 < Kd; k0 += 16) {
        for (int l = tid; l < 128*16; l += 256) {
            int r = l / 16, c = l % 16;
            As[c][r] = g_ctx[(size_t)(bm + r) * Kd + k0 + c];
        }
        for (int l = tid; l < 16*128; l += 256) {
            int r = l / 128, c = l % 128;
            Bs[r][c] = w[(size_t)(k0 + r) * Nout + bn + c];
        }
        __syncthreads();
        #pragma unroll
        for (int k = 0; k < 16; k++) {
            float ra[8], rb[8];
            #pragma unroll
            for (int i = 0; i < 8; i++) ra[i] = As[k][ty*8 + i];
            #pragma unroll
            for (int j = 0; j < 8; j++) rb[j] = Bs[k][tx*8 + j];
            #pragma unroll
            for (int i = 0; i < 8; i++)
                #pragma unroll
                for (int j = 0; j < 8; j++)
                    acc[i][j] += ra[i] * rb[j];
        }
        __syncthreads();
    }
    #pragma unroll
    for (int i = 0; i < 8; i++) {
        int row = bm + ty*8 + i;
        #pragma unroll
        for (int j = 0; j < 8; j++) {
            int col = bn + tx*8 + j;
            out[(size_t)row * Nout + col] = acc[i][j] + bias[col];
        }
    }
}

// =====================================================================
extern "C" void kernel_launch(void* const* d_in, const int* in_sizes, int n_in,
                              void* d_out, int out_size) {
    const float* x     = (const float*)d_in[0];
    const float* w_qkv = (const float*)d_in[1];
    const float* b_qkv = (const float*)d_in[2];
    const float* th1   = (const float*)d_in[3];
    const float* th2   = (const float*)d_in[4];
    const float* w_out = (const float*)d_in[5];
    const float* b_out = (const float*)d_in[6];
    float* out = (float*)d_out;

    // idempotent; needed for 64KB dynamic smem in softmax_mix
    cudaFuncSetAttribute(softmax_mix, cudaFuncAttributeMaxDynamicSharedMemorySize, 65536);

    dim3 t(256);
    gemm_qkv<<<dim3(QKVN/128, (BB*NN)/128), t>>>(x, w_qkv, b_qkv);
    gemm_qk <<<dim3(NN/128, NN/128, BB*HH), t>>>();
    softmax_mix<<<dim3(BB*NN), t, 65536>>>(th1, th2);
    gemm_av <<<dim3(1, NN/128, BB*HH), t>>>();
    gemm_out<<<dim3(DIMM/128, (BB*NN)/128), t>>>(w_out, b_out, out);
}

// round 4
// speedup vs baseline: 2.0480x; 2.0480x over previous
#include <cuda_runtime.h>
#include <cuda_bf16.h>
#include <math.h>
#include <stdint.h>

#define BB 4
#define NN 2048
#define DIMM 512
#define HH 8
#define DHH 64
#define QKVN 1536
#define QKK 192            // 3 * 64 (bf16 split-K: [hi|lo|hi] x [hi|hi|lo])
#define ATTN_SCALE 0.125f

// ---------------- scratch (device globals; allocation-free rule) ----------------
__device__ float g_q[BB*HH*NN*DHH];                 // [bh][n][d] fp32
__device__ float g_k[BB*HH*NN*DHH];
__device__ float g_v[BB*HH*NN*DHH];
__device__ __nv_bfloat16 gA_qk[(size_t)BB*HH*NN*QKK];   // [bh][n][192]
__device__ __nv_bfloat16 gB_qk[(size_t)BB*HH*NN*QKK];   // [bh][m][192]
__device__ __nv_bfloat16 gVh[BB*HH*NN*DHH];         // [bh][m][64]
__device__ __nv_bfloat16 gVl[BB*HH*NN*DHH];
__device__ float g_dots[(size_t)BB*NN*HH*NN];       // [b][n][h][m]
__device__ __nv_bfloat16 g_ah[(size_t)BB*HH*NN*NN]; // attn hi [b][g][n][m]
__device__ __nv_bfloat16 g_al[(size_t)BB*HH*NN*NN]; // attn lo
__device__ float g_ctx[BB*NN*HH*DHH];               // [b][n][g*64+d]

// ======================= PTX helpers (sm_80-baseline; no tcgen05) =======================
__device__ __forceinline__ uint32_t smem_u32(const void* p) {
    uint32_t a;
    asm("{ .reg .u64 t; cvta.to.shared.u64 t, %1; cvt.u32.u64 %0, t; }" : "=r"(a) : "l"(p));
    return a;
}
#define LDSM_X4(r, addr) \
    asm volatile("ldmatrix.sync.aligned.m8n8.x4.shared.b16 {%0,%1,%2,%3}, [%4];" \
        : "=r"((r)[0]), "=r"((r)[1]), "=r"((r)[2]), "=r"((r)[3]) : "r"(addr))
#define LDSM_X4_T(r0, r1, r2, r3, addr) \
    asm volatile("ldmatrix.sync.aligned.m8n8.x4.trans.shared.b16 {%0,%1,%2,%3}, [%4];" \
        : "=r"(r0), "=r"(r1), "=r"(r2), "=r"(r3) : "r"(addr))
#define MMA_BF16(c, a, b) \
    asm volatile("mma.sync.aligned.m16n8k16.row.col.f32.bf16.bf16.f32 " \
        "{%0,%1,%2,%3}, {%4,%5,%6,%7}, {%8,%9}, {%0,%1,%2,%3};" \
        : "+f"((c)[0]), "+f"((c)[1]), "+f"((c)[2]), "+f"((c)[3]) \
        : "r"((a)[0]), "r"((a)[1]), "r"((a)[2]), "r"((a)[3]), "r"((b)[0]), "r"((b)[1]))

__device__ __forceinline__ uint32_t pack_bf2(__nv_bfloat16 lo, __nv_bfloat16 hi) {
    return ((uint32_t)__bfloat16_as_ushort(hi) << 16) | (uint32_t)__bfloat16_as_ushort(lo);
}

// =====================================================================
// K1: qkv = x(8192x512) @ w(512x1536) + bias  -> scatter to q/k/v [bh][n][d]
// =====================================================================
__global__ __launch_bounds__(256) void gemm_qkv(const float* __restrict__ x,
                                                const float* __restrict__ w,
                                                const float* __restrict__ bias) {
    __shared__ float As[16][132];
    __shared__ float Bs[16][132];
    int bm = blockIdx.y * 128, bn = blockIdx.x * 128;
    int tid = threadIdx.x;
    int tx = tid % 16, ty = tid / 16;
    float acc[8][8] = {};
    for (int k0 = 0; k0 < DIMM; k0 += 16) {
        for (int idx = tid; idx < 512; idx += 256) {
            int r = idx >> 2, c4 = idx & 3;
            float4 v = *(const float4*)(x + (size_t)(bm + r) * DIMM + k0 + c4 * 4);
            As[c4*4+0][r] = v.x; As[c4*4+1][r] = v.y; As[c4*4+2][r] = v.z; As[c4*4+3][r] = v.w;
        }
        for (int idx = tid; idx < 512; idx += 256) {
            int r = idx >> 5, c4 = idx & 31;
            *(float4*)&Bs[r][c4*4] = *(const float4*)(w + (size_t)(k0 + r) * QKVN + bn + c4 * 4);
        }
        __syncthreads();
        #pragma unroll
        for (int k = 0; k < 16; k++) {
            float4 a0 = *(float4*)&As[k][ty*8], a1 = *(float4*)&As[k][ty*8+4];
            float4 b0 = *(float4*)&Bs[k][tx*8], b1 = *(float4*)&Bs[k][tx*8+4];
            float ra[8] = {a0.x,a0.y,a0.z,a0.w,a1.x,a1.y,a1.z,a1.w};
            float rb[8] = {b0.x,b0.y,b0.z,b0.w,b1.x,b1.y,b1.z,b1.w};
            #pragma unroll
            for (int i = 0; i < 8; i++)
                #pragma unroll
                for (int j = 0; j < 8; j++)
                    acc[i][j] += ra[i] * rb[j];
        }
        __syncthreads();
    }
    int which = bn / 512;
    float* dst_base = (which == 0) ? g_q : (which == 1) ? g_k : g_v;
    int colr = bn % 512;
    float4 bia0 = *(const float4*)(bias + bn + tx*8);
    float4 bia1 = *(const float4*)(bias + bn + tx*8 + 4);
    #pragma unroll
    for (int i = 0; i < 8; i++) {
        int row = bm + ty*8 + i;
        int b_ = row >> 11, n_ = row & (NN - 1);
        #pragma unroll
        for (int half = 0; half < 2; half++) {
            int c0 = colr + tx*8 + half*4;
            int hh = c0 >> 6, dd = c0 & 63;
            float4 bi = half ? bia1 : bia0;
            float4 o;
            o.x = acc[i][half*4+0] + bi.x; o.y = acc[i][half*4+1] + bi.y;
            o.z = acc[i][half*4+2] + bi.z; o.w = acc[i][half*4+3] + bi.w;
            *(float4*)(dst_base + (((size_t)(b_*HH + hh)) * NN + n_) * DHH + dd) = o;
        }
    }
}

// =====================================================================
// K1b: build bf16 split operands.  A'=[qh|ql|qh]*scale, B'=[kh|kh|kl]; V hi/lo.
// =====================================================================
__global__ __launch_bounds__(256) void convert_qk() {
    size_t t = (size_t)blockIdx.x * 256 + threadIdx.x;   // 1,048,576 threads
    int d4 = (int)(t & 15);
    size_t rest = t >> 4;
    int n = (int)(rest & (NN - 1));
    int bh = (int)(rest >> 11);
    size_t src = ((size_t)bh * NN + n) * DHH + d4 * 4;
    float4 q = *(const float4*)(g_q + src);
    float4 kk = *(const float4*)(g_k + src);
    float4 vv = *(const float4*)(g_v + src);
    q.x *= ATTN_SCALE; q.y *= ATTN_SCALE; q.z *= ATTN_SCALE; q.w *= ATTN_SCALE;
    union BF4 { uint2 u; __nv_bfloat16 h[4]; };
    BF4 qh, ql, kh, kl, vh, vl;
    float qa[4] = {q.x, q.y, q.z, q.w};
    float ka[4] = {kk.x, kk.y, kk.z, kk.w};
    float va[4] = {vv.x, vv.y, vv.z, vv.w};
    #pragma unroll
    for (int j = 0; j < 4; j++) {
        qh.h[j] = __float2bfloat16(qa[j]);
        ql.h[j] = __float2bfloat16(qa[j] - __bfloat162float(qh.h[j]));
        kh.h[j] = __float2bfloat16(ka[j]);
        kl.h[j] = __float2bfloat16(ka[j] - __bfloat162float(kh.h[j]));
        vh.h[j] = __float2bfloat16(va[j]);
        vl.h[j] = __float2bfloat16(va[j] - __bfloat162float(vh.h[j]));
    }
    size_t rb = ((size_t)bh * NN + n) * QKK;
    *(uint2*)(gA_qk + rb +       d4*4) = qh.u;
    *(uint2*)(gA_qk + rb +  64 + d4*4) = ql.u;
    *(uint2*)(gA_qk + rb + 128 + d4*4) = qh.u;
    *(uint2*)(gB_qk + rb +       d4*4) = kh.u;
    *(uint2*)(gB_qk + rb +  64 + d4*4) = kh.u;
    *(uint2*)(gB_qk + rb + 128 + d4*4) = kl.u;
    *(uint2*)(gVh + src) = vh.u;
    *(uint2*)(gVl + src) = vl.u;
}

// =====================================================================
// K2: QK^T via mma.sync bf16.  CTA tile 128(n) x 128(m), K=192 resident in smem.
// 8 warps (4m x 2n), warp tile 32x64. grid (16,16,32).
// =====================================================================
#define QK_SA 200   // smem row stride in bf16 (400B: 16B-aligned)
#define QK_SMEM_BYTES (2 * 128 * QK_SA * 2)   // 102400

__global__ __launch_bounds__(256, 2) void qk_mma() {
    extern __shared__ __nv_bfloat16 sm_qk[];
    __nv_bfloat16* As = sm_qk;                 // [128][QK_SA]
    __nv_bfloat16* Bs = sm_qk + 128 * QK_SA;
    int tid = threadIdx.x, lane = tid & 31, wid = tid >> 5;
    int wm = wid >> 1, wn = wid & 1;
    int bh = blockIdx.z;
    int b_ = bh >> 3, h_ = bh & 7;
    int bn = blockIdx.x * 128;   // m (cols of dots)
    int bm = blockIdx.y * 128;   // n (rows of dots)

    const __nv_bfloat16* Ag = gA_qk + ((size_t)bh * NN + bm) * QKK;
    const __nv_bfloat16* Bg = gB_qk + ((size_t)bh * NN + bn) * QKK;
    for (int i = tid; i < 128 * 24; i += 256) {
        int r = i / 24, c = (i % 24) * 8;
        *(uint4*)(As + r * QK_SA + c) = *(const uint4*)(Ag + (size_t)r * QKK + c);
        *(uint4*)(Bs + r * QK_SA + c) = *(const uint4*)(Bg + (size_t)r * QKK + c);
    }
    __syncthreads();

    uint32_t a_u = smem_u32(As);
    uint32_t b_u = smem_u32(Bs);
    uint32_t lrow = lane & 15;             // ldmatrix row within 16
    uint32_t lcol = (lane >> 4) * 8;       // ldmatrix col-half

    float acc[2][8][4] = {};
    #pragma unroll
    for (int ks = 0; ks < 12; ks++) {
        int k0 = ks * 16;
        uint32_t af[2][4];
        #pragma unroll
        for (int pm = 0; pm < 2; pm++) {
            uint32_t addr = a_u + (((wm*32 + pm*16 + lrow) * QK_SA) + k0 + lcol) * 2;
            LDSM_X4(af[pm], addr);
        }
        uint32_t bf[8][2];
        #pragma unroll
        for (int np2 = 0; np2 < 4; np2++) {
            uint32_t r0, r1, r2, r3;
            uint32_t addr = b_u + (((wn*64 + np2*16 + lrow) * QK_SA) + k0 + lcol) * 2;
            asm volatile("ldmatrix.sync.aligned.m8n8.x4.shared.b16 {%0,%1,%2,%3}, [%4];"
                : "=r"(r0), "=r"(r1), "=r"(r2), "=r"(r3) : "r"(addr));
            bf[np2*2][0] = r0; bf[np2*2+1][0] = r1;
            bf[np2*2][1] = r2; bf[np2*2+1][1] = r3;
        }
        #pragma unroll
        for (int pm = 0; pm < 2; pm++)
            #pragma unroll
            for (int pn = 0; pn < 8; pn++)
                MMA_BF16(acc[pm][pn], af[pm], bf[pn]);
    }

    // epilogue -> g_dots [b][n][h][m]
    int row0 = bm + wm*32 + (lane >> 2);
    int col0 = bn + wn*64 + (lane & 3) * 2;
    #pragma unroll
    for (int pm = 0; pm < 2; pm++) {
        #pragma unroll
        for (int pn = 0; pn < 8; pn++) {
            int r = row0 + pm*16;
            int c = col0 + pn*8;
            float* p0 = g_dots + ((size_t)(b_*NN + r) * HH + h_) * NN + c;
            float2 v0 = {acc[pm][pn][0], acc[pm][pn][1]};
            *(float2*)p0 = v0;
            float* p1 = g_dots + ((size_t)(b_*NN + r + 8) * HH + h_) * NN + c;
            float2 v1 = {acc[pm][pn][2], acc[pm][pn][3]};
            *(float2*)p1 = v1;
        }
    }
}

// =====================================================================
// K3: per (b,n): th1-mix, softmax over m, th2-mix (1/sum folded), emit bf16 hi/lo
// =====================================================================
__global__ __launch_bounds__(256) void softmax_mix(const float* __restrict__ th1,
                                                   const float* __restrict__ th2) {
    extern __shared__ float s2[];                  // [8][2048]
    __shared__ float th1s[64], th2s[64], cgh[64];
    __shared__ float redm[64], reds[64], gmax[8], rowsum[8];
    int bid = blockIdx.x;
    int b_ = bid >> 11, n_ = bid & (NN - 1);
    int tid = threadIdx.x, warp = tid >> 5, lane = tid & 31;
    if (tid < 64) { th1s[tid] = th1[tid]; th2s[tid] = th2[tid]; }
    __syncthreads();
    const float4* drow4 = (const float4*)(g_dots + ((size_t)(b_ * NN + n_)) * HH * NN);
    float4* s4 = (float4*)s2;

    // phase 1: pre-softmax head mixing
    for (int m4 = tid; m4 < NN/4; m4 += 256) {
        float4 dv[HH];
        #pragma unroll
        for (int h = 0; h < HH; h++) dv[h] = drow4[h * (NN/4) + m4];
        #pragma unroll
        for (int g = 0; g < HH; g++) {
            float4 s = {0.f, 0.f, 0.f, 0.f};
            #pragma unroll
            for (int h = 0; h < HH; h++) {
                float w = th1s[g*HH + h];
                s.x += w * dv[h].x; s.y += w * dv[h].y;
                s.z += w * dv[h].z; s.w += w * dv[h].w;
            }
            s4[g * (NN/4) + m4] = s;
        }
    }
    __syncthreads();

    // phase 2a: max per mixed head
    float mx[HH];
    #pragma unroll
    for (int g = 0; g < HH; g++) {
        float4 u = s4[g * (NN/4) + tid*2];
        float4 v = s4[g * (NN/4) + tid*2 + 1];
        float m1 = fmaxf(fmaxf(u.x, u.y), fmaxf(u.z, u.w));
        float m2 = fmaxf(fmaxf(v.x, v.y), fmaxf(v.z, v.w));
        mx[g] = fmaxf(m1, m2);
    }
    #pragma unroll
    for (int off = 16; off > 0; off >>= 1)
        #pragma unroll
        for (int g = 0; g < HH; g++)
            mx[g] = fmaxf(mx[g], __shfl_xor_sync(0xFFFFFFFF, mx[g], off));
    if (lane == 0)
        #pragma unroll
        for (int g = 0; g < HH; g++) redm[warp*8 + g] = mx[g];
    __syncthreads();
    if (tid < 8) {
        float m = redm[tid];
        #pragma unroll
        for (int w = 1; w < 8; w++) m = fmaxf(m, redm[w*8 + tid]);
        gmax[tid] = m;
    }
    __syncthreads();

    // phase 2b: exp + sum
    float sm_[HH];
    #pragma unroll
    for (int g = 0; g < HH; g++) {
        float gm = gmax[g];
        float4 u = s4[g * (NN/4) + tid*2];
        float4 v = s4[g * (NN/4) + tid*2 + 1];
        u.x = __expf(u.x - gm); u.y = __expf(u.y - gm);
        u.z = __expf(u.z - gm); u.w = __expf(u.w - gm);
        v.x = __expf(v.x - gm); v.y = __expf(v.y - gm);
        v.z = __expf(v.z - gm); v.w = __expf(v.w - gm);
        s4[g * (NN/4) + tid*2] = u;
        s4[g * (NN/4) + tid*2 + 1] = v;
        sm_[g] = (u.x + u.y + u.z + u.w) + (v.x + v.y + v.z + v.w);
    }
    #pragma unroll
    for (int off = 16; off > 0; off >>= 1)
        #pragma unroll
        for (int g = 0; g < HH; g++)
            sm_[g] += __shfl_xor_sync(0xFFFFFFFF, sm_[g], off);
    if (lane == 0)
        #pragma unroll
        for (int g = 0; g < HH; g++) reds[warp*8 + g] = sm_[g];
    __syncthreads();
    if (tid < 8) {
        float s = 0.f;
        #pragma unroll
        for (int w = 0; w < 8; w++) s += reds[w*8 + tid];
        rowsum[tid] = s;
    }
    __syncthreads();
    if (tid < 64) cgh[tid] = th2s[tid] / rowsum[tid & 7];
    __syncthreads();

    // phase 3: post-softmax mixing -> bf16 hi/lo attn [b][g][n][m]
    for (int m4 = tid; m4 < NN/4; m4 += 256) {
        float4 ev[HH];
        #pragma unroll
        for (int h = 0; h < HH; h++) ev[h] = s4[h * (NN/4) + m4];
        #pragma unroll
        for (int g = 0; g < HH; g++) {
            float4 s = {0.f, 0.f, 0.f, 0.f};
            #pragma unroll
            for (int h = 0; h < HH; h++) {
                float w = cgh[g*HH + h];
                s.x += w * ev[h].x; s.y += w * ev[h].y;
                s.z += w * ev[h].z; s.w += w * ev[h].w;
            }
            __nv_bfloat16 hx = __float2bfloat16(s.x), hy = __float2bfloat16(s.y);
            __nv_bfloat16 hz = __float2bfloat16(s.z), hw = __float2bfloat16(s.w);
            __nv_bfloat16 lx = __float2bfloat16(s.x - __bfloat162float(hx));
            __nv_bfloat16 ly = __float2bfloat16(s.y - __bfloat162float(hy));
            __nv_bfloat16 lz = __float2bfloat16(s.z - __bfloat162float(hz));
            __nv_bfloat16 lw = __float2bfloat16(s.w - __bfloat162float(hw));
            size_t base = (((size_t)(b_*HH + g)) * NN + n_) * NN + m4*4;
            uint2 hu = {pack_bf2(hx, hy), pack_bf2(hz, hw)};
            uint2 lu = {pack_bf2(lx, ly), pack_bf2(lz, lw)};
            *(uint2*)(g_ah + base) = hu;
            *(uint2*)(g_al + base) = lu;
        }
    }
}

// =====================================================================
// K4: AV via mma.sync bf16 split: ctx = Ah@Vh + Al@Vh + Ah@Vl.
// CTA tile 256(n) x 64(d), K=2048 double-buffered k=16 stages.
// 8 warps (4m x 2n), warp tile 64x32. grid (8, 32).
// =====================================================================
#define AV_SA 24                    // A smem stride (bf16): 48B
#define AV_SV 72                    // V smem stride (bf16): 144B (64 data + 8 pad)
#define AV_AT (256*AV_SA)           // 6144 bf16
#define AV_VT (16*AV_SV)            // 1152 bf16
#define AV_STG (2*AV_AT + 2*AV_VT)  // 14592 bf16 per stage
#define AV_SMEM_BYTES (2 * AV_STG * 2)   // 58368

__global__ __launch_bounds__(256) void av_mma() {
    extern __shared__ __nv_bfloat16 sm_av[];
    int tid = threadIdx.x, lane = tid & 31, wid = tid >> 5;
    int wm = wid >> 1, wn = wid & 1;
    int bg = blockIdx.y;
    int b_ = bg >> 3, g_ = bg & 7;
    int bm = blockIdx.x * 256;

    const __nv_bfloat16* Ah = g_ah + (size_t)bg * NN * NN;
    const __nv_bfloat16* Al = g_al + (size_t)bg * NN * NN;
    const __nv_bfloat16* Vh = gVh + (size_t)bg * NN * DHH;
    const __nv_bfloat16* Vl = gVl + (size_t)bg * NN * DHH;

    auto load_stage = [&](int s, int k0) {
        __nv_bfloat16* base = sm_av + s * AV_STG;
        #pragma unroll
        for (int i = tid; i < 512; i += 256) {
            int r = i >> 1, c = (i & 1) * 8;
            *(uint4*)(base + r*AV_SA + c) = *(const uint4*)(Ah + (size_t)(bm + r) * NN + k0 + c);
            *(uint4*)(base + AV_AT + r*AV_SA + c) = *(const uint4*)(Al + (size_t)(bm + r) * NN + k0 + c);
        }
        {
            int i = tid;                      // 256 chunks: 128 hi + 128 lo
            int half = i >> 7;
            int j = i & 127;
            int r = j >> 3, c = (j & 7) * 8;
            const __nv_bfloat16* src = half ? Vl : Vh;
            *(uint4*)(base + 2*AV_AT + half*AV_VT + r*AV_SV + c) =
                *(const uint4*)(src + (size_t)(k0 + r) * DHH + c);
        }
    };

    float acc[4][4][4] = {};
    load_stage(0, 0);
    uint32_t lrow = lane & 15;
    uint32_t lcol = (lane >> 4) * 8;
    uint32_t vkr = ((lane >> 3) & 1) * 8 + (lane & 7);

    for (int it = 0; it < NN/16; it++) {
        __syncthreads();
        if (it + 1 < NN/16) load_stage((it + 1) & 1, (it + 1) * 16);
        __nv_bfloat16* base = sm_av + (it & 1) * AV_STG;
        uint32_t a_u  = smem_u32(base);
        uint32_t al_u = a_u + AV_AT * 2;
        uint32_t vh_u = a_u + 4 * AV_AT;        // bytes
        uint32_t vl_u = vh_u + AV_VT * 2;

        uint32_t vh[4][2], vl[4][2];
        #pragma unroll
        for (int half = 0; half < 2; half++) {
            uint32_t nc = wn*32 + half*16 + (lane >> 4) * 8;
            uint32_t r0, r1, r2, r3;
            LDSM_X4_T(r0, r1, r2, r3, vh_u + (vkr * AV_SV + nc) * 2);
            vh[half*2][0] = r0; vh[half*2][1] = r1;
            vh[half*2+1][0] = r2; vh[half*2+1][1] = r3;
            LDSM_X4_T(r0, r1, r2, r3, vl_u + (vkr * AV_SV + nc) * 2);
            vl[half*2][0] = r0; vl[half*2][1] = r1;
            vl[half*2+1][0] = r2; vl[half*2+1][1] = r3;
        }
        #pragma unroll
        for (int pm = 0; pm < 4; pm++) {
            uint32_t arow = wm*64 + pm*16 + lrow;
            uint32_t af[4];
            LDSM_X4(af, a_u + (arow * AV_SA + lcol) * 2);
            #pragma unroll
            for (int pn = 0; pn < 4; pn++) {
                MMA_BF16(acc[pm][pn], af, vh[pn]);
                MMA_BF16(acc[pm][pn], af, vl[pn]);
            }
            LDSM_X4(af, al_u + (arow * AV_SA + lcol) * 2);
            #pragma unroll
            for (int pn = 0; pn < 4; pn++)
                MMA_BF16(acc[pm][pn], af, vh[pn]);
        }
    }

    // epilogue -> g_ctx [b][n][g*64+d]
    int row0 = bm + wm*64 + (lane >> 2);
    int col0 = wn*32 + (lane & 3) * 2;
    #pragma unroll
    for (int pm = 0; pm < 4; pm++) {
        #pragma unroll
        for (int pn = 0; pn < 4; pn++) {
            int r = row0 + pm*16;
            int c = col0 + pn*8;
            float* p0 = g_ctx + ((size_t)(b_*NN + r)) * (HH*DHH) + g_*DHH + c;
            float2 v0 = {acc[pm][pn][0], acc[pm][pn][1]};
            *(float2*)p0 = v0;
            float* p1 = g_ctx + ((size_t)(b_*NN + r + 8)) * (HH*DHH) + g_*DHH + c;
            float2 v1 = {acc[pm][pn][2], acc[pm][pn][3]};
            *(float2*)p1 = v1;
        }
    }
}

// =====================================================================
// K5: y = ctx(8192x512) @ w_out(512x512) + b_out
// =====================================================================
__global__ __launch_bounds__(256) void gemm_out(const float* __restrict__ w,
                                                const float* __restrict__ bias,
                                                float* __restrict__ out) {
    __shared__ float As[16][132];
    __shared__ float Bs[16][132];
    int bm = blockIdx.y * 128, bn = blockIdx.x * 128;
    int tid = threadIdx.x;
    int tx = tid % 16, ty = tid / 16;
    const int Kd = HH * DHH;
    float acc[8][8] = {};
    for (int k0 = 0; k0 < Kd; k0 += 16) {
        for (int idx = tid; idx < 512; idx += 256) {
            int r = idx >> 2, c4 = idx & 3;
            float4 v = *(const float4*)(g_ctx + (size_t)(bm + r) * Kd + k0 + c4 * 4);
            As[c4*4+0][r] = v.x; As[c4*4+1][r] = v.y; As[c4*4+2][r] = v.z; As[c4*4+3][r] = v.w;
        }
        for (int idx = tid; idx < 512; idx += 256) {
            int r = idx >> 5, c4 = idx & 31;
            *(float4*)&Bs[r][c4*4] = *(const float4*)(w + (size_t)(k0 + r) * DIMM + bn + c4 * 4);
        }
        __syncthreads();
        #pragma unroll
        for (int k = 0; k < 16; k++) {
            float4 a0 = *(float4*)&As[k][ty*8], a1 = *(float4*)&As[k][ty*8+4];
            float4 b0 = *(float4*)&Bs[k][tx*8], b1 = *(float4*)&Bs[k][tx*8+4];
            float ra[8] = {a0.x,a0.y,a0.z,a0.w,a1.x,a1.y,a1.z,a1.w};
            float rb[8] = {b0.x,b0.y,b0.z,b0.w,b1.x,b1.y,b1.z,b1.w};
            #pragma unroll
            for (int i = 0; i < 8; i++)
                #pragma unroll
                for (int j = 0; j < 8; j++)
                    acc[i][j] += ra[i] * rb[j];
        }
        __syncthreads();
    }
    float4 bia0 = *(const float4*)(bias + bn + tx*8);
    float4 bia1 = *(const float4*)(bias + bn + tx*8 + 4);
    #pragma unroll
    for (int i = 0; i < 8; i++) {
        int row = bm + ty*8 + i;
        float4 o0 = {acc[i][0]+bia0.x, acc[i][1]+bia0.y, acc[i][2]+bia0.z, acc[i][3]+bia0.w};
        float4 o1 = {acc[i][4]+bia1.x, acc[i][5]+bia1.y, acc[i][6]+bia1.z, acc[i][7]+bia1.w};
        *(float4*)(out + (size_t)row * DIMM + bn + tx*8) = o0;
        *(float4*)(out + (size_t)row * DIMM + bn + tx*8 + 4) = o1;
    }
}

// =====================================================================
extern "C" void kernel_launch(void* const* d_in, const int* in_sizes, int n_in,
                              void* d_out, int out_size) {
    const float* x     = (const float*)d_in[0];
    const float* w_qkv = (const float*)d_in[1];
    const float* b_qkv = (const float*)d_in[2];
    const float* th1   = (const float*)d_in[3];
    const float* th2   = (const float*)d_in[4];
    const float* w_out = (const float*)d_in[5];
    const float* b_out = (const float*)d_in[6];
    float* out = (float*)d_out;

    cudaFuncSetAttribute(softmax_mix, cudaFuncAttributeMaxDynamicSharedMemorySize, 65536);
    cudaFuncSetAttribute(qk_mma, cudaFuncAttributeMaxDynamicSharedMemorySize, QK_SMEM_BYTES);
    cudaFuncSetAttribute(av_mma, cudaFuncAttributeMaxDynamicSharedMemorySize, AV_SMEM_BYTES);

    gemm_qkv<<<dim3(QKVN/128, (BB*NN)/128), 256>>>(x, w_qkv, b_qkv);
    convert_qk<<<4096, 256>>>();
    qk_mma<<<dim3(NN/128, NN/128, BB*HH), 256, QK_SMEM_BYTES>>>();
    softmax_mix<<<dim3(BB*NN), 256, 65536>>>(th1, th2);
    av_mma<<<dim3(NN/256, BB*HH), 256, AV_SMEM_BYTES>>>();
    gemm_out<<<dim3(DIMM/128, (BB*NN)/128), 256>>>(w_out, b_out, out);
}

// round 5
// speedup vs baseline: 2.6009x; 1.2700x over previous
#include <cuda_runtime.h>
#include <cuda_bf16.h>
#include <math.h>
#include <stdint.h>

#define BB 4
#define NN 2048
#define DIMM 512
#define HH 8
#define DHH 64
#define QKVN 1536
#define QKK 192            // 3 * 64 (bf16 split-K: [hi|lo|hi] x [hi|hi|lo])
#define ATTN_SCALE 0.125f

// ---------------- scratch (device globals; allocation-free rule) ----------------
__device__ __nv_bfloat16 gXh[BB*NN*DIMM], gXl[BB*NN*DIMM];          // x hi/lo [8192][512]
__device__ __nv_bfloat16 gWqh[DIMM*QKVN], gWql[DIMM*QKVN];          // w_qkv hi/lo [512][1536]
__device__ __nv_bfloat16 gWoh[DIMM*DIMM], gWol[DIMM*DIMM];          // w_out hi/lo [512][512]
__device__ __nv_bfloat16 gA_qk[(size_t)BB*HH*NN*QKK];               // [bh][n][192]
__device__ __nv_bfloat16 gB_qk[(size_t)BB*HH*NN*QKK];               // [bh][m][192]
__device__ __nv_bfloat16 gVh[BB*HH*NN*DHH], gVl[BB*HH*NN*DHH];      // [bh][m][64]
__device__ float g_dots[(size_t)BB*NN*HH*NN];                       // [b][n][h][m]
__device__ __nv_bfloat16 g_ah[(size_t)BB*HH*NN*NN];                 // attn hi [b][g][n][m]
__device__ __nv_bfloat16 g_al[(size_t)BB*HH*NN*NN];                 // attn lo
__device__ __nv_bfloat16 gCh[BB*NN*HH*DHH], gCl[BB*NN*HH*DHH];      // ctx hi/lo [8192][512]

// ======================= PTX helpers =======================
__device__ __forceinline__ uint32_t smem_u32(const void* p) {
    uint32_t a;
    asm("{ .reg .u64 t; cvta.to.shared.u64 t, %1; cvt.u32.u64 %0, t; }" : "=r"(a) : "l"(p));
    return a;
}
#define LDSM_X4(r, addr) \
    asm volatile("ldmatrix.sync.aligned.m8n8.x4.shared.b16 {%0,%1,%2,%3}, [%4];" \
        : "=r"((r)[0]), "=r"((r)[1]), "=r"((r)[2]), "=r"((r)[3]) : "r"(addr))
#define LDSM_X4_T(r0, r1, r2, r3, addr) \
    asm volatile("ldmatrix.sync.aligned.m8n8.x4.trans.shared.b16 {%0,%1,%2,%3}, [%4];" \
        : "=r"(r0), "=r"(r1), "=r"(r2), "=r"(r3) : "r"(addr))
#define MMA_BF16(c, a, b) \
    asm volatile("mma.sync.aligned.m16n8k16.row.col.f32.bf16.bf16.f32 " \
        "{%0,%1,%2,%3}, {%4,%5,%6,%7}, {%8,%9}, {%0,%1,%2,%3};" \
        : "+f"((c)[0]), "+f"((c)[1]), "+f"((c)[2]), "+f"((c)[3]) \
        : "r"((a)[0]), "r"((a)[1]), "r"((a)[2]), "r"((a)[3]), "r"((b)[0]), "r"((b)[1]))

__device__ __forceinline__ uint32_t pack_bf2(__nv_bfloat16 lo, __nv_bfloat16 hi) {
    return ((uint32_t)__bfloat16_as_ushort(hi) << 16) | (uint32_t)__bfloat16_as_ushort(lo);
}
__device__ __forceinline__ void split_bf(float v, __nv_bfloat16& h, __nv_bfloat16& l) {
    h = __float2bfloat16(v);
    l = __float2bfloat16(v - __bfloat162float(h));
}

// =====================================================================
// K0: convert x, w_qkv, w_out to bf16 hi/lo.  float4-granular, 3 sections.
// =====================================================================
#define CV_X  (BB*NN*DIMM/4)       // 1048576
#define CV_WQ (DIMM*QKVN/4)        // 196608
#define CV_WO (DIMM*DIMM/4)        // 65536
__global__ __launch_bounds__(256) void conv_inputs(const float* __restrict__ x,
                                                   const float* __restrict__ wq,
                                                   const float* __restrict__ wo) {
    int i = blockIdx.x * 256 + threadIdx.x;
    const float* src; __nv_bfloat16 *dh, *dl; int off;
    if (i < CV_X)              { src = x;  dh = gXh;  dl = gXl;  off = i; }
    else if (i < CV_X + CV_WQ) { src = wq; dh = gWqh; dl = gWql; off = i - CV_X; }
    else                       { src = wo; dh = gWoh; dl = gWol; off = i - CV_X - CV_WQ; }
    float4 v = ((const float4*)src)[off];
    __nv_bfloat16 h0,l0,h1,l1,h2,l2,h3,l3;
    split_bf(v.x,h0,l0); split_bf(v.y,h1,l1); split_bf(v.z,h2,l2); split_bf(v.w,h3,l3);
    uint2 hu = {pack_bf2(h0,h1), pack_bf2(h2,h3)};
    uint2 lu = {pack_bf2(l0,l1), pack_bf2(l2,l3)};
    *(uint2*)(dh + (size_t)off*4) = hu;
    *(uint2*)(dl + (size_t)off*4) = lu;
}

// =====================================================================
// K1: QKV projection via mma.sync 3-term split.  M=8192, N=1536, K=3*512.
// Tile 128x128, 8 warps (4m x 2n), double-buffered k=32 stages.
// Epilogue: +bias, scatter bf16 hi/lo into gA_qk / gB_qk / gVh / gVl.
// =====================================================================
#define PJ_SA 40    // A stage stride (bf16): 80B
#define PJ_SB 136   // B stage stride (bf16): 272B
#define PJ_STG (128*PJ_SA + 32*PJ_SB)   // 9472 bf16 per stage

__global__ __launch_bounds__(256) void qkv_mma(const float* __restrict__ bias) {
    __shared__ __nv_bfloat16 sm[2*PJ_STG];
    int tid = threadIdx.x, lane = tid & 31, wid = tid >> 5;
    int wm = wid >> 1, wn = wid & 1;
    int bm = blockIdx.y * 128, bn = blockIdx.x * 128;

    auto load_stage = [&](int s, int ck) {
        int seg = ck >> 4, kloc = (ck & 15) * 32;
        __nv_bfloat16* A = sm + s * PJ_STG;
        __nv_bfloat16* B = A + 128 * PJ_SA;
        const __nv_bfloat16* Asrc = (seg == 1) ? gXl : gXh;
        const __nv_bfloat16* Bsrc = (seg == 2) ? gWql : gWqh;
        #pragma unroll
        for (int i = tid; i < 512; i += 256) {
            int r = i >> 2, c = (i & 3) * 8;
            *(uint4*)(A + r*PJ_SA + c) = *(const uint4*)(Asrc + (size_t)(bm + r) * DIMM + kloc + c);
        }
        #pragma unroll
        for (int i = tid; i < 512; i += 256) {
            int r = i >> 4, c = (i & 15) * 8;
            *(uint4*)(B + r*PJ_SB + c) = *(const uint4*)(Bsrc + (size_t)(kloc + r) * QKVN + bn + c);
        }
    };

    float acc[2][8][4] = {};
    load_stage(0, 0);
    uint32_t lrow = lane & 15, lcol = (lane >> 4) * 8;
    uint32_t vkr = ((lane >> 3) & 1) * 8 + (lane & 7);

    for (int ck = 0; ck < 48; ck++) {
        __syncthreads();
        if (ck + 1 < 48) load_stage((ck + 1) & 1, ck + 1);
        uint32_t a_u = smem_u32(sm + (ck & 1) * PJ_STG);
        uint32_t b_u = a_u + 128 * PJ_SA * 2;
        #pragma unroll
        for (int ks = 0; ks < 2; ks++) {
            int k0 = ks * 16;
            uint32_t af[2][4];
            #pragma unroll
            for (int pm = 0; pm < 2; pm++)
                LDSM_X4(af[pm], a_u + ((wm*32 + pm*16 + lrow) * PJ_SA + k0 + lcol) * 2);
            uint32_t bf[8][2];
            #pragma unroll
            for (int q = 0; q < 4; q++) {
                uint32_t r0, r1, r2, r3;
                LDSM_X4_T(r0, r1, r2, r3, b_u + ((k0 + vkr) * PJ_SB + wn*64 + q*16 + lcol) * 2);
                bf[q*2][0] = r0; bf[q*2][1] = r1;
                bf[q*2+1][0] = r2; bf[q*2+1][1] = r3;
            }
            #pragma unroll
            for (int pm = 0; pm < 2; pm++)
                #pragma unroll
                for (int pn = 0; pn < 8; pn++)
                    MMA_BF16(acc[pm][pn], af[pm], bf[pn]);
        }
    }

    int row0 = bm + wm*32 + (lane >> 2);
    int col0 = bn + wn*64 + (lane & 3) * 2;
    #pragma unroll
    for (int pm = 0; pm < 2; pm++) {
        #pragma unroll
        for (int pn = 0; pn < 8; pn++) {
            int c = col0 + pn*8;
            int which = c >> 9, cw = c & 511, hh = cw >> 6, dd = cw & 63;
            float b0 = bias[c], b1 = bias[c+1];
            #pragma unroll
            for (int half = 0; half < 2; half++) {
                int r = row0 + pm*16 + half*8;
                float v0 = acc[pm][pn][half*2+0] + b0;
                float v1 = acc[pm][pn][half*2+1] + b1;
                int b_ = r >> 11, n_ = r & (NN - 1);
                int bh = b_*HH + hh;
                __nv_bfloat16 h0,l0,h1,l1;
                if (which == 0) {
                    v0 *= ATTN_SCALE; v1 *= ATTN_SCALE;
                    split_bf(v0,h0,l0); split_bf(v1,h1,l1);
                    size_t rb = ((size_t)bh * NN + n_) * QKK;
                    uint32_t hp = pack_bf2(h0,h1), lp = pack_bf2(l0,l1);
                    *(uint32_t*)(gA_qk + rb + dd) = hp;
                    *(uint32_t*)(gA_qk + rb + 64 + dd) = lp;
                    *(uint32_t*)(gA_qk + rb + 128 + dd) = hp;
                } else if (which == 1) {
                    split_bf(v0,h0,l0); split_bf(v1,h1,l1);
                    size_t rb = ((size_t)bh * NN + n_) * QKK;
                    uint32_t hp = pack_bf2(h0,h1), lp = pack_bf2(l0,l1);
                    *(uint32_t*)(gB_qk + rb + dd) = hp;
                    *(uint32_t*)(gB_qk + rb + 64 + dd) = hp;
                    *(uint32_t*)(gB_qk + rb + 128 + dd) = lp;
                } else {
                    split_bf(v0,h0,l0); split_bf(v1,h1,l1);
                    size_t rb = ((size_t)bh * NN + n_) * DHH + dd;
                    *(uint32_t*)(gVh + rb) = pack_bf2(h0,h1);
                    *(uint32_t*)(gVl + rb) = pack_bf2(l0,l1);
                }
            }
        }
    }
}

// =====================================================================
// K2: QK^T via mma.sync bf16 (verified round 4).  CTA 128x128, K=192.
// =====================================================================
#define QK_SA 200
#define QK_SMEM_BYTES (2 * 128 * QK_SA * 2)   // 102400

__global__ __launch_bounds__(256, 2) void qk_mma() {
    extern __shared__ __nv_bfloat16 sm_qk[];
    __nv_bfloat16* As = sm_qk;
    __nv_bfloat16* Bs = sm_qk + 128 * QK_SA;
    int tid = threadIdx.x, lane = tid & 31, wid = tid >> 5;
    int wm = wid >> 1, wn = wid & 1;
    int bh = blockIdx.z;
    int b_ = bh >> 3, h_ = bh & 7;
    int bn = blockIdx.x * 128;
    int bm = blockIdx.y * 128;

    const __nv_bfloat16* Ag = gA_qk + ((size_t)bh * NN + bm) * QKK;
    const __nv_bfloat16* Bg = gB_qk + ((size_t)bh * NN + bn) * QKK;
    for (int i = tid; i < 128 * 24; i += 256) {
        int r = i / 24, c = (i % 24) * 8;
        *(uint4*)(As + r * QK_SA + c) = *(const uint4*)(Ag + (size_t)r * QKK + c);
        *(uint4*)(Bs + r * QK_SA + c) = *(const uint4*)(Bg + (size_t)r * QKK + c);
    }
    __syncthreads();

    uint32_t a_u = smem_u32(As);
    uint32_t b_u = smem_u32(Bs);
    uint32_t lrow = lane & 15;
    uint32_t lcol = (lane >> 4) * 8;

    float acc[2][8][4] = {};
    #pragma unroll
    for (int ks = 0; ks < 12; ks++) {
        int k0 = ks * 16;
        uint32_t af[2][4];
        #pragma unroll
        for (int pm = 0; pm < 2; pm++)
            LDSM_X4(af[pm], a_u + (((wm*32 + pm*16 + lrow) * QK_SA) + k0 + lcol) * 2);
        uint32_t bf[8][2];
        #pragma unroll
        for (int np2 = 0; np2 < 4; np2++) {
            uint32_t r0, r1, r2, r3;
            uint32_t addr = b_u + (((wn*64 + np2*16 + lrow) * QK_SA) + k0 + lcol) * 2;
            asm volatile("ldmatrix.sync.aligned.m8n8.x4.shared.b16 {%0,%1,%2,%3}, [%4];"
                : "=r"(r0), "=r"(r1), "=r"(r2), "=r"(r3) : "r"(addr));
            bf[np2*2][0] = r0; bf[np2*2+1][0] = r1;
            bf[np2*2][1] = r2; bf[np2*2+1][1] = r3;
        }
        #pragma unroll
        for (int pm = 0; pm < 2; pm++)
            #pragma unroll
            for (int pn = 0; pn < 8; pn++)
                MMA_BF16(acc[pm][pn], af[pm], bf[pn]);
    }

    int row0 = bm + wm*32 + (lane >> 2);
    int col0 = bn + wn*64 + (lane & 3) * 2;
    #pragma unroll
    for (int pm = 0; pm < 2; pm++) {
        #pragma unroll
        for (int pn = 0; pn < 8; pn++) {
            int r = row0 + pm*16;
            int c = col0 + pn*8;
            float* p0 = g_dots + ((size_t)(b_*NN + r) * HH + h_) * NN + c;
            float2 v0 = {acc[pm][pn][0], acc[pm][pn][1]};
            *(float2*)p0 = v0;
            float* p1 = g_dots + ((size_t)(b_*NN + r + 8) * HH + h_) * NN + c;
            float2 v1 = {acc[pm][pn][2], acc[pm][pn][3]};
            *(float2*)p1 = v1;
        }
    }
}

// =====================================================================
// K3: register-resident softmax+mix.  Thread owns 8 m-positions x 8 heads.
// =====================================================================
__global__ __launch_bounds__(256) void softmax_mix(const float* __restrict__ th1,
                                                   const float* __restrict__ th2) {
    __shared__ float th1s[64], th2s[64], cgh[64], red[64], gmax[8];
    int bid = blockIdx.x;
    int b_ = bid >> 11, n_ = bid & (NN - 1);
    int tid = threadIdx.x, warp = tid >> 5, lane = tid & 31;
    if (tid < 64) { th1s[tid] = th1[tid]; th2s[tid] = th2[tid]; }
    __syncthreads();
    const float4* drow4 = (const float4*)(g_dots + ((size_t)(b_ * NN + n_)) * HH * NN);

    float v[8][8];
    #pragma unroll
    for (int h = 0; h < 8; h++) {
        float4 a = drow4[h * (NN/4) + tid*2];
        float4 b = drow4[h * (NN/4) + tid*2 + 1];
        v[h][0]=a.x; v[h][1]=a.y; v[h][2]=a.z; v[h][3]=a.w;
        v[h][4]=b.x; v[h][5]=b.y; v[h][6]=b.z; v[h][7]=b.w;
    }
    #pragma unroll
    for (int m = 0; m < 8; m++) {
        float t[8];
        #pragma unroll
        for (int h = 0; h < 8; h++) t[h] = v[h][m];
        #pragma unroll
        for (int g = 0; g < 8; g++) {
            float s = 0.f;
            #pragma unroll
            for (int h = 0; h < 8; h++) s += th1s[g*8 + h] * t[h];
            v[g][m] = s;
        }
    }
    float mg[8];
    #pragma unroll
    for (int g = 0; g < 8; g++) {
        float m = v[g][0];
        #pragma unroll
        for (int j = 1; j < 8; j++) m = fmaxf(m, v[g][j]);
        mg[g] = m;
    }
    #pragma unroll
    for (int off = 16; off > 0; off >>= 1)
        #pragma unroll
        for (int g = 0; g < 8; g++)
            mg[g] = fmaxf(mg[g], __shfl_xor_sync(0xFFFFFFFF, mg[g], off));
    if (lane == 0)
        #pragma unroll
        for (int g = 0; g < 8; g++) red[warp*8 + g] = mg[g];
    __syncthreads();
    if (tid < 8) {
        float m = red[tid];
        #pragma unroll
        for (int w = 1; w < 8; w++) m = fmaxf(m, red[w*8 + tid]);
        gmax[tid] = m;
    }
    __syncthreads();
    float sg[8];
    #pragma unroll
    for (int g = 0; g < 8; g++) {
        float gm = gmax[g];
        float s = 0.f;
        #pragma unroll
        for (int j = 0; j < 8; j++) {
            v[g][j] = __expf(v[g][j] - gm);
            s += v[g][j];
        }
        sg[g] = s;
    }
    #pragma unroll
    for (int off = 16; off > 0; off >>= 1)
        #pragma unroll
        for (int g = 0; g < 8; g++)
            sg[g] += __shfl_xor_sync(0xFFFFFFFF, sg[g], off);
    __syncthreads();
    if (lane == 0)
        #pragma unroll
        for (int g = 0; g < 8; g++) red[warp*8 + g] = sg[g];
    __syncthreads();
    if (tid < 64) {
        int col = tid & 7;
        float s = 0.f;
        #pragma unroll
        for (int w = 0; w < 8; w++) s += red[w*8 + col];
        cgh[tid] = th2s[tid] / s;
    }
    __syncthreads();
    #pragma unroll
    for (int gp = 0; gp < 8; gp++) {
        float o[8];
        #pragma unroll
        for (int m = 0; m < 8; m++) {
            float s = 0.f;
            #pragma unroll
            for (int g = 0; g < 8; g++) s += cgh[gp*8 + g] * v[g][m];
            o[m] = s;
        }
        uint32_t hw[4], lw[4];
        #pragma unroll
        for (int j = 0; j < 4; j++) {
            __nv_bfloat16 h0,l0,h1,l1;
            split_bf(o[2*j], h0, l0);
            split_bf(o[2*j+1], h1, l1);
            hw[j] = pack_bf2(h0, h1);
            lw[j] = pack_bf2(l0, l1);
        }
        size_t base = (((size_t)(b_*HH + gp)) * NN + n_) * NN + (size_t)tid*8;
        uint4 hv = {hw[0], hw[1], hw[2], hw[3]};
        uint4 lv = {lw[0], lw[1], lw[2], lw[3]};
        *(uint4*)(g_ah + base) = hv;
        *(uint4*)(g_al + base) = lv;
    }
}

// =====================================================================
// K4: AV via mma.sync bf16 split (verified).  Epilogue emits ctx hi/lo.
// =====================================================================
#define AV_SA 24
#define AV_SV 72
#define AV_AT (256*AV_SA)
#define AV_VT (16*AV_SV)
#define AV_STG (2*AV_AT + 2*AV_VT)
#define AV_SMEM_BYTES (2 * AV_STG * 2)

__global__ __launch_bounds__(256) void av_mma() {
    extern __shared__ __nv_bfloat16 sm_av[];
    int tid = threadIdx.x, lane = tid & 31, wid = tid >> 5;
    int wm = wid >> 1, wn = wid & 1;
    int bg = blockIdx.y;
    int b_ = bg >> 3, g_ = bg & 7;
    int bm = blockIdx.x * 256;

    const __nv_bfloat16* Ah = g_ah + (size_t)bg * NN * NN;
    const __nv_bfloat16* Al = g_al + (size_t)bg * NN * NN;
    const __nv_bfloat16* Vh = gVh + (size_t)bg * NN * DHH;
    const __nv_bfloat16* Vl = gVl + (size_t)bg * NN * DHH;

    auto load_stage = [&](int s, int k0) {
        __nv_bfloat16* base = sm_av + s * AV_STG;
        #pragma unroll
        for (int i = tid; i < 512; i += 256) {
            int r = i >> 1, c = (i & 1) * 8;
            *(uint4*)(base + r*AV_SA + c) = *(const uint4*)(Ah + (size_t)(bm + r) * NN + k0 + c);
            *(uint4*)(base + AV_AT + r*AV_SA + c) = *(const uint4*)(Al + (size_t)(bm + r) * NN + k0 + c);
        }
        {
            int i = tid;
            int half = i >> 7;
            int j = i & 127;
            int r = j >> 3, c = (j & 7) * 8;
            const __nv_bfloat16* src = half ? Vl : Vh;
            *(uint4*)(base + 2*AV_AT + half*AV_VT + r*AV_SV + c) =
                *(const uint4*)(src + (size_t)(k0 + r) * DHH + c);
        }
    };

    float acc[4][4][4] = {};
    load_stage(0, 0);
    uint32_t lrow = lane & 15;
    uint32_t lcol = (lane >> 4) * 8;
    uint32_t vkr = ((lane >> 3) & 1) * 8 + (lane & 7);

    for (int it = 0; it < NN/16; it++) {
        __syncthreads();
        if (it + 1 < NN/16) load_stage((it + 1) & 1, (it + 1) * 16);
        __nv_bfloat16* base = sm_av + (it & 1) * AV_STG;
        uint32_t a_u  = smem_u32(base);
        uint32_t al_u = a_u + AV_AT * 2;
        uint32_t vh_u = a_u + 4 * AV_AT;
        uint32_t vl_u = vh_u + AV_VT * 2;

        uint32_t vh[4][2], vl[4][2];
        #pragma unroll
        for (int half = 0; half < 2; half++) {
            uint32_t nc = wn*32 + half*16 + (lane >> 4) * 8;
            uint32_t r0, r1, r2, r3;
            LDSM_X4_T(r0, r1, r2, r3, vh_u + (vkr * AV_SV + nc) * 2);
            vh[half*2][0] = r0; vh[half*2][1] = r1;
            vh[half*2+1][0] = r2; vh[half*2+1][1] = r3;
            LDSM_X4_T(r0, r1, r2, r3, vl_u + (vkr * AV_SV + nc) * 2);
            vl[half*2][0] = r0; vl[half*2][1] = r1;
            vl[half*2+1][0] = r2; vl[half*2+1][1] = r3;
        }
        #pragma unroll
        for (int pm = 0; pm < 4; pm++) {
            uint32_t arow = wm*64 + pm*16 + lrow;
            uint32_t af[4];
            LDSM_X4(af, a_u + (arow * AV_SA + lcol) * 2);
            #pragma unroll
            for (int pn = 0; pn < 4; pn++) {
                MMA_BF16(acc[pm][pn], af, vh[pn]);
                MMA_BF16(acc[pm][pn], af, vl[pn]);
            }
            LDSM_X4(af, al_u + (arow * AV_SA + lcol) * 2);
            #pragma unroll
            for (int pn = 0; pn < 4; pn++)
                MMA_BF16(acc[pm][pn], af, vh[pn]);
        }
    }

    int row0 = bm + wm*64 + (lane >> 2);
    int col0 = wn*32 + (lane & 3) * 2;
    #pragma unroll
    for (int pm = 0; pm < 4; pm++) {
        #pragma unroll
        for (int pn = 0; pn < 4; pn++) {
            int c = col0 + pn*8;
            #pragma unroll
            for (int half = 0; half < 2; half++) {
                int r = row0 + pm*16 + half*8;
                float v0 = acc[pm][pn][half*2+0];
                float v1 = acc[pm][pn][half*2+1];
                __nv_bfloat16 h0,l0,h1,l1;
                split_bf(v0,h0,l0); split_bf(v1,h1,l1);
                size_t rb = ((size_t)(b_*NN + r)) * (HH*DHH) + g_*DHH + c;
                *(uint32_t*)(gCh + rb) = pack_bf2(h0,h1);
                *(uint32_t*)(gCl + rb) = pack_bf2(l0,l1);
            }
        }
    }
}

// =====================================================================
// K5: out projection via mma.sync 3-term split.  M=8192, N=512, K=3*512.
// =====================================================================
__global__ __launch_bounds__(256) void out_mma(const float* __restrict__ bias,
                                               float* __restrict__ out) {
    __shared__ __nv_bfloat16 sm[2*PJ_STG];
    int tid = threadIdx.x, lane = tid & 31, wid = tid >> 5;
    int wm = wid >> 1, wn = wid & 1;
    int bm = blockIdx.y * 128, bn = blockIdx.x * 128;

    auto load_stage = [&](int s, int ck) {
        int seg = ck >> 4, kloc = (ck & 15) * 32;
        __nv_bfloat16* A = sm + s * PJ_STG;
        __nv_bfloat16* B = A + 128 * PJ_SA;
        const __nv_bfloat16* Asrc = (seg == 1) ? gCl : gCh;
        const __nv_bfloat16* Bsrc = (seg == 2) ? gWol : gWoh;
        #pragma unroll
        for (int i = tid; i < 512; i += 256) {
            int r = i >> 2, c = (i & 3) * 8;
            *(uint4*)(A + r*PJ_SA + c) = *(const uint4*)(Asrc + (size_t)(bm + r) * DIMM + kloc + c);
        }
        #pragma unroll
        for (int i = tid; i < 512; i += 256) {
            int r = i >> 4, c = (i & 15) * 8;
            *(uint4*)(B + r*PJ_SB + c) = *(const uint4*)(Bsrc + (size_t)(kloc + r) * DIMM + bn + c);
        }
    };

    float acc[2][8][4] = {};
    load_stage(0, 0);
    uint32_t lrow = lane & 15, lcol = (lane >> 4) * 8;
    uint32_t vkr = ((lane >> 3) & 1) * 8 + (lane & 7);

    for (int ck = 0; ck < 48; ck++) {
        __syncthreads();
        if (ck + 1 < 48) load_stage((ck + 1) & 1, ck + 1);
        uint32_t a_u = smem_u32(sm + (ck & 1) * PJ_STG);
        uint32_t b_u = a_u + 128 * PJ_SA * 2;
        #pragma unroll
        for (int ks = 0; ks < 2; ks++) {
            int k0 = ks * 16;
            uint32_t af[2][4];
            #pragma unroll
            for (int pm = 0; pm < 2; pm++)
                LDSM_X4(af[pm], a_u + ((wm*32 + pm*16 + lrow) * PJ_SA + k0 + lcol) * 2);
            uint32_t bf[8][2];
            #pragma unroll
            for (int q = 0; q < 4; q++) {
                uint32_t r0, r1, r2, r3;
                LDSM_X4_T(r0, r1, r2, r3, b_u + ((k0 + vkr) * PJ_SB + wn*64 + q*16 + lcol) * 2);
                bf[q*2][0] = r0; bf[q*2][1] = r1;
                bf[q*2+1][0] = r2; bf[q*2+1][1] = r3;
            }
            #pragma unroll
            for (int pm = 0; pm < 2; pm++)
                #pragma unroll
                for (int pn = 0; pn < 8; pn++)
                    MMA_BF16(acc[pm][pn], af[pm], bf[pn]);
        }
    }

    int row0 = bm + wm*32 + (lane >> 2);
    int col0 = bn + wn*64 + (lane & 3) * 2;
    #pragma unroll
    for (int pm = 0; pm < 2; pm++) {
        #pragma unroll
        for (int pn = 0; pn < 8; pn++) {
            int c = col0 + pn*8;
            float b0 = bias[c], b1 = bias[c+1];
            #pragma unroll
            for (int half = 0; half < 2; half++) {
                int r = row0 + pm*16 + half*8;
                float2 st = {acc[pm][pn][half*2+0] + b0, acc[pm][pn][half*2+1] + b1};
                *(float2*)(out + (size_t)r * DIMM + c) = st;
            }
        }
    }
}

// =====================================================================
extern "C" void kernel_launch(void* const* d_in, const int* in_sizes, int n_in,
                              void* d_out, int out_size) {
    const float* x     = (const float*)d_in[0];
    const float* w_qkv = (const float*)d_in[1];
    const float* b_qkv = (const float*)d_in[2];
    const float* th1   = (const float*)d_in[3];
    const float* th2   = (const float*)d_in[4];
    const float* w_out = (const float*)d_in[5];
    const float* b_out = (const float*)d_in[6];
    float* out = (float*)d_out;

    cudaFuncSetAttribute(qk_mma, cudaFuncAttributeMaxDynamicSharedMemorySize, QK_SMEM_BYTES);
    cudaFuncSetAttribute(av_mma, cudaFuncAttributeMaxDynamicSharedMemorySize, AV_SMEM_BYTES);

    conv_inputs<<<(CV_X + CV_WQ + CV_WO) / 256, 256>>>(x, w_qkv, w_out);
    qkv_mma<<<dim3(QKVN/128, (BB*NN)/128), 256>>>(b_qkv);
    qk_mma<<<dim3(NN/128, NN/128, BB*HH), 256, QK_SMEM_BYTES>>>();
    softmax_mix<<<BB*NN, 256>>>(th1, th2);
    av_mma<<<dim3(NN/256, BB*HH), 256, AV_SMEM_BYTES>>>();
    out_mma<<<dim3(DIMM/128, (BB*NN)/128), 256>>>(b_out, out);
}